// round 1
// baseline (speedup 1.0000x reference)
#include <cuda_runtime.h>
#include <cuda_bf16.h>
#include <cstdint>

// Problem constants (from reference): N=100000 nodes, D=256 features, E=3200000 edges.
// Scratch must be __device__ globals (no allocation allowed anywhere).
#define MAX_N 100000
#define FEAT_D 256

__device__ float g_diag[MAX_N];   // sigmoid(x @ w + b)
__device__ float g_deg[MAX_N];    // degree over col
__device__ int   g_is64;          // 1 if edge_index is int64, 0 if int32

// ---------------------------------------------------------------------------
// Probe: detect index width. For int64 little-endian values < 2^32, every odd
// 32-bit word is zero. For int32, odd words are random indices in [0, N) and
// are ~never all zero over 256 samples. Single warp, negligible cost.
// ---------------------------------------------------------------------------
__global__ void probe_kernel(const int* __restrict__ ei_words) {
    int nz = 0;
    for (int i = threadIdx.x; i < 256; i += 32) {
        if (ei_words[2 * i + 1] != 0) nz++;
    }
    #pragma unroll
    for (int o = 16; o; o >>= 1) nz += __shfl_xor_sync(0xFFFFFFFFu, nz, o);
    if (threadIdx.x == 0) g_is64 = (nz == 0) ? 1 : 0;
}

// ---------------------------------------------------------------------------
// K1: diag[i] = sigmoid(dot(x[i,:], w) + b); also zero g_deg.
// One warp per row; each lane loads 2 float4 of x and w (w is L1-resident).
// ---------------------------------------------------------------------------
__global__ void diag_kernel(const float* __restrict__ x,
                            const float* __restrict__ w,
                            const float* __restrict__ b,
                            int n) {
    int gtid = blockIdx.x * blockDim.x + threadIdx.x;
    if (gtid < n) g_deg[gtid] = 0.0f;           // independent of dot-product work

    int warp = gtid >> 5;
    int lane = threadIdx.x & 31;
    if (warp >= n) return;

    const float4* xr = reinterpret_cast<const float4*>(x + (size_t)warp * FEAT_D);
    const float4* w4 = reinterpret_cast<const float4*>(w);

    float4 a0 = xr[lane];
    float4 a1 = xr[lane + 32];
    float4 w0 = __ldg(&w4[lane]);
    float4 w1 = __ldg(&w4[lane + 32]);

    float s = a0.x * w0.x + a0.y * w0.y + a0.z * w0.z + a0.w * w0.w
            + a1.x * w1.x + a1.y * w1.y + a1.z * w1.z + a1.w * w1.w;

    #pragma unroll
    for (int o = 16; o; o >>= 1) s += __shfl_xor_sync(0xFFFFFFFFu, s, o);

    if (lane == 0) {
        float z = s + __ldg(b);
        g_diag[warp] = 1.0f / (1.0f + expf(-z));
    }
}

// ---------------------------------------------------------------------------
// K2: degree count over col (second half of edge_index). Scattered float
// atomics into a 400 KB L2-resident array.
// ---------------------------------------------------------------------------
__global__ void deg_kernel(const void* __restrict__ eidx, int E) {
    int base = (blockIdx.x * blockDim.x + threadIdx.x) * 4;
    if (base >= E) return;
    if (g_is64) {
        const long long* col = reinterpret_cast<const long long*>(eidx) + E;
        #pragma unroll
        for (int k = 0; k < 4; k++) {
            int e = base + k;
            if (e < E) atomicAdd(&g_deg[(int)col[e]], 1.0f);
        }
    } else {
        const int* col = reinterpret_cast<const int*>(eidx) + E;
        if (base + 3 < E) {
            int4 c = *reinterpret_cast<const int4*>(col + base);
            atomicAdd(&g_deg[c.x], 1.0f);
            atomicAdd(&g_deg[c.y], 1.0f);
            atomicAdd(&g_deg[c.z], 1.0f);
            atomicAdd(&g_deg[c.w], 1.0f);
        } else {
            for (int e = base; e < E; e++) atomicAdd(&g_deg[col[e]], 1.0f);
        }
    }
}

// ---------------------------------------------------------------------------
// K3: adj_val[e] = (1/deg[row[e]]) * attr[e] * diag[col[e]]; write output.
// mode3: out = [row (as float) | col (as float) | vals], each length E.
// else : out = vals only.
// ---------------------------------------------------------------------------
__global__ void val_kernel(const void* __restrict__ eidx,
                           const float* __restrict__ attr,
                           float* __restrict__ out,
                           int E, int mode3) {
    int base = (blockIdx.x * blockDim.x + threadIdx.x) * 4;
    if (base >= E) return;

    int r[4], c[4];
    bool full = (base + 3 < E);

    if (g_is64) {
        const long long* R = reinterpret_cast<const long long*>(eidx);
        const long long* C = R + E;
        #pragma unroll
        for (int k = 0; k < 4; k++) {
            int e = full ? base + k : min(base + k, E - 1);
            r[k] = (int)R[e];
            c[k] = (int)C[e];
        }
    } else {
        const int* R = reinterpret_cast<const int*>(eidx);
        const int* C = R + E;
        if (full) {
            int4 ri = *reinterpret_cast<const int4*>(R + base);
            int4 ci = *reinterpret_cast<const int4*>(C + base);
            r[0] = ri.x; r[1] = ri.y; r[2] = ri.z; r[3] = ri.w;
            c[0] = ci.x; c[1] = ci.y; c[2] = ci.z; c[3] = ci.w;
        } else {
            #pragma unroll
            for (int k = 0; k < 4; k++) {
                int e = min(base + k, E - 1);
                r[k] = R[e]; c[k] = C[e];
            }
        }
    }

    float a[4];
    if (full) {
        float4 av = *reinterpret_cast<const float4*>(attr + base);
        a[0] = av.x; a[1] = av.y; a[2] = av.z; a[3] = av.w;
    } else {
        #pragma unroll
        for (int k = 0; k < 4; k++) a[k] = attr[min(base + k, E - 1)];
    }

    float v[4];
    #pragma unroll
    for (int k = 0; k < 4; k++) {
        float dinv = 1.0f / __ldg(&g_deg[r[k]]);
        v[k] = dinv * a[k] * __ldg(&g_diag[c[k]]);
    }

    if (mode3) {
        if (full) {
            float4 rf = make_float4((float)r[0], (float)r[1], (float)r[2], (float)r[3]);
            float4 cf = make_float4((float)c[0], (float)c[1], (float)c[2], (float)c[3]);
            float4 vf = make_float4(v[0], v[1], v[2], v[3]);
            *reinterpret_cast<float4*>(out + base)             = rf;
            *reinterpret_cast<float4*>(out + (size_t)E + base) = cf;
            *reinterpret_cast<float4*>(out + (size_t)2 * E + base) = vf;
        } else {
            for (int e = base; e < E; e++) {
                int k = e - base;
                out[e]               = (float)r[k];
                out[(size_t)E + e]   = (float)c[k];
                out[(size_t)2*E + e] = v[k];
            }
        }
    } else {
        if (full) {
            *reinterpret_cast<float4*>(out + base) = make_float4(v[0], v[1], v[2], v[3]);
        } else {
            for (int e = base; e < E; e++) out[e] = v[e - base];
        }
    }
}

// ---------------------------------------------------------------------------
// Launch. Inputs (metadata order): x [N*D] f32, edge_index [2*E] int,
// edge_attr [E] f32, w [D] f32, b [1] f32.
// ---------------------------------------------------------------------------
extern "C" void kernel_launch(void* const* d_in, const int* in_sizes, int n_in,
                              void* d_out, int out_size) {
    const float* x    = (const float*)d_in[0];
    const void*  ei   = d_in[1];
    const float* attr = (const float*)d_in[2];
    const float* w    = (const float*)d_in[3];
    const float* b    = (const float*)d_in[4];
    float* out = (float*)d_out;

    int E = in_sizes[2];                 // edge count from edge_attr
    int N = in_sizes[0] / FEAT_D;        // node count from x

    int mode3 = (out_size >= 3 * E) ? 1 : 0;

    // 1) detect int32 vs int64 edge_index
    probe_kernel<<<1, 32>>>((const int*)ei);

    // 2) diag + zero deg: one warp per node, 8 warps per block
    int diag_blocks = (N + 7) / 8;
    diag_kernel<<<diag_blocks, 256>>>(x, w, b, N);

    // 3) degree atomics: 4 edges per thread
    int ethreads = (E + 3) / 4;
    int eblocks  = (ethreads + 255) / 256;
    deg_kernel<<<eblocks, 256>>>(ei, E);

    // 4) values + output
    val_kernel<<<eblocks, 256>>>(ei, attr, out, E, mode3);
}